// round 1
// baseline (speedup 1.0000x reference)
#include <cuda_runtime.h>
#include <math.h>

#define NN    8192
#define NHID  1024
#define NFEAT 63

// ---------------- scratch (device globals; no allocation allowed) ----------
__device__ float g_h  [NN * NHID];
__device__ float g_h0 [NN * NHID];
__device__ float g_hi [NN * NHID];
__device__ float g_sup[NN * NHID];
__device__ float g_hp [NN * NHID];
__device__ float g_s1 [NN];
__device__ float g_s2 [NN];
__device__ float g_att[(size_t)NN * NN];   // 256 MB
__device__ float g_h64[NN * 64];

// ---------------- SGEMM: C = A(MxK) * B(KxN), fused epilogues --------------
// EPI 0: C = acc
// EPI 1: C = relu(theta*acc + (1-theta)*S + H)
// EPI 2: C = elu (theta*acc + (1-theta)*S + H)
#define BM 128
#define BN 128
#define BK 8
#define TM 8
#define TN 8

template<int EPI>
__global__ void __launch_bounds__(256)
sgemm_kernel(const float* __restrict__ A, const float* __restrict__ B,
             float* __restrict__ C, int M, int N, int K,
             const float* __restrict__ S, const float* __restrict__ H,
             float theta)
{
    __shared__ float As[BK][BM];
    __shared__ float Bs[BK][BN];

    const int bm = blockIdx.y, bn = blockIdx.x;
    const int tid = threadIdx.x;
    const int tx = tid & 15, ty = tid >> 4;

    const float* Ablk = A + (size_t)bm * BM * K;
    const float* Bblk = B + bn * BN;

    float acc[TM][TN];
    #pragma unroll
    for (int i = 0; i < TM; i++)
        #pragma unroll
        for (int j = 0; j < TN; j++) acc[i][j] = 0.f;

    const int arow = tid >> 1;            // 0..127
    const int aseg = (tid & 1) * 4;       // 0 or 4
    const int brow = tid >> 5;            // 0..7
    const int bcol = (tid & 31) * 4;      // 0..124

    for (int k0 = 0; k0 < K; k0 += BK) {
        float4 av = *(const float4*)(Ablk + (size_t)arow * K + k0 + aseg);
        As[aseg + 0][arow] = av.x;
        As[aseg + 1][arow] = av.y;
        As[aseg + 2][arow] = av.z;
        As[aseg + 3][arow] = av.w;
        float4 bv = *(const float4*)(Bblk + (size_t)(k0 + brow) * N + bcol);
        *(float4*)&Bs[brow][bcol] = bv;
        __syncthreads();

        #pragma unroll
        for (int k = 0; k < BK; k++) {
            float ra[TM], rb[TN];
            #pragma unroll
            for (int i = 0; i < TM; i++) ra[i] = As[k][ty * TM + i];
            #pragma unroll
            for (int j = 0; j < TN; j++) rb[j] = Bs[k][tx * TN + j];
            #pragma unroll
            for (int i = 0; i < TM; i++)
                #pragma unroll
                for (int j = 0; j < TN; j++)
                    acc[i][j] = fmaf(ra[i], rb[j], acc[i][j]);
        }
        __syncthreads();
    }

    const int row0 = bm * BM + ty * TM;
    const int col0 = bn * BN + tx * TN;
    const float omt = 1.0f - theta;
    #pragma unroll
    for (int i = 0; i < TM; i++) {
        size_t base = (size_t)(row0 + i) * N + col0;
        #pragma unroll
        for (int j = 0; j < TN; j++) {
            size_t idx = base + j;
            float a = acc[i][j];
            if (EPI == 0) {
                C[idx] = a;
            } else {
                float v = theta * a + omt * S[idx] + H[idx];
                if (EPI == 1) C[idx] = fmaxf(v, 0.f);
                else          C[idx] = (v > 0.f) ? v : (expf(v) - 1.f);
            }
        }
    }
}

// ---------------- fc: h = relu(x @ fc_W + b), also copy to h0 --------------
__global__ void fc_kernel(const float* __restrict__ x, const float* __restrict__ W,
                          const float* __restrict__ b, float* __restrict__ h,
                          float* __restrict__ h0)
{
    int row = blockIdx.x;
    __shared__ float xs[NFEAT];
    int t = threadIdx.x;                      // 256
    if (t < NFEAT) xs[t] = x[row * NFEAT + t];
    __syncthreads();
    for (int n = t; n < NHID; n += 256) {
        float acc = b[n];
        #pragma unroll 7
        for (int k = 0; k < NFEAT; k++) acc = fmaf(xs[k], W[k * NHID + n], acc);
        float v = fmaxf(acc, 0.f);
        size_t idx = (size_t)row * NHID + n;
        h[idx] = v;
        h0[idx] = v;
    }
}

// ---------------- support = 0.3*hi + 0.7*h0 --------------------------------
__global__ void support_kernel(const float* __restrict__ hi, const float* __restrict__ h0,
                               float* __restrict__ sup, int n4)
{
    int i = blockIdx.x * blockDim.x + threadIdx.x;
    int stride = gridDim.x * blockDim.x;
    const float4* a = (const float4*)hi;
    const float4* b = (const float4*)h0;
    float4* o = (float4*)sup;
    for (; i < n4; i += stride) {
        float4 u = a[i], v = b[i], r;
        r.x = 0.3f * u.x + 0.7f * v.x;
        r.y = 0.3f * u.y + 0.7f * v.y;
        r.z = 0.3f * u.z + 0.7f * v.z;
        r.w = 0.3f * u.w + 0.7f * v.w;
        o[i] = r;
    }
}

// ---------------- GAT score vectors: s1 = hp@a1, s2 = hp@a2 ----------------
__global__ void gat_s_kernel(const float* __restrict__ hp, const float* __restrict__ a,
                             float* __restrict__ s1, float* __restrict__ s2)
{
    int row = blockIdx.x;
    int t = threadIdx.x;                      // 256
    float p1 = 0.f, p2 = 0.f;
    const float* hrow = hp + (size_t)row * NHID;
    for (int k = t; k < NHID; k += 256) {
        float v = hrow[k];
        p1 = fmaf(v, a[k], p1);
        p2 = fmaf(v, a[NHID + k], p2);
    }
    __shared__ float r1[256], r2[256];
    r1[t] = p1; r2[t] = p2;
    __syncthreads();
    for (int off = 128; off > 0; off >>= 1) {
        if (t < off) { r1[t] += r1[t + off]; r2[t] += r2[t + off]; }
        __syncthreads();
    }
    if (t == 0) { s1[row] = r1[0]; s2[row] = r2[0]; }
}

// ---------------- masked row softmax -> attention matrix -------------------
__global__ void att_kernel(const int* __restrict__ adj, const float* __restrict__ s1,
                           const float* __restrict__ s2, float* __restrict__ A)
{
    int row = blockIdx.x;
    int t = threadIdx.x;                      // 256
    float si = s1[row];
    const int* arow = adj + (size_t)row * NN;

    float m = -1e30f, ssum = 0.f;
    for (int j = t; j < NN; j += 256) {
        if (arow[j] > 0) {
            float e = si + s2[j];
            e = (e > 0.f) ? e : 0.2f * e;
            if (e > m) { ssum = ssum * expf(m - e); m = e; }
            ssum += expf(e - m);
        }
    }
    __shared__ float sm[256], ss[256];
    sm[t] = m; ss[t] = ssum;
    __syncthreads();
    for (int off = 128; off > 0; off >>= 1) {
        if (t < off) {
            float m2 = sm[t + off], sv = ss[t + off];
            float M = fmaxf(sm[t], m2);
            ss[t] = ss[t] * expf(sm[t] - M) + sv * expf(m2 - M);
            sm[t] = M;
        }
        __syncthreads();
    }
    float M = sm[0], S = ss[0];
    float inv = (S > 0.f) ? (1.f / S) : 0.f;

    float* Arow = A + (size_t)row * NN;
    for (int j = t; j < NN; j += 256) {
        float val = 0.f;
        if (arow[j] > 0) {
            float e = si + s2[j];
            e = (e > 0.f) ? e : 0.2f * e;
            val = expf(e - M) * inv;
        }
        Arow[j] = val;
    }
}

// ---------------- classifier layer 1: relu(h @ cls1_W + b), N=64 -----------
__global__ void cls1_kernel(const float* __restrict__ h, const float* __restrict__ W,
                            const float* __restrict__ b, float* __restrict__ out)
{
    int row = blockIdx.x;
    int t = threadIdx.x;                      // 64
    __shared__ float hs[NHID];
    for (int k = t; k < NHID; k += 64) hs[k] = h[(size_t)row * NHID + k];
    __syncthreads();
    float acc = b[t];
    for (int k = 0; k < NHID; k++) acc = fmaf(hs[k], W[k * 64 + t], acc);
    out[row * 64 + t] = fmaxf(acc, 0.f);
}

// ---------------- classifier layer 2: sigmoid(h64 @ cls3_W + b) ------------
__global__ void cls3_kernel(const float* __restrict__ h64, const float* __restrict__ W,
                            const float* __restrict__ b, float* __restrict__ out)
{
    int i = blockIdx.x * blockDim.x + threadIdx.x;
    if (i < NN) {
        float acc = b[0];
        #pragma unroll 16
        for (int k = 0; k < 64; k++) acc = fmaf(h64[i * 64 + k], W[k], acc);
        out[i] = 1.f / (1.f + expf(-acc));
    }
}

// ---------------------------------------------------------------------------
extern "C" void kernel_launch(void* const* d_in, const int* in_sizes, int n_in,
                              void* d_out, int out_size)
{
    const float* x      = (const float*)d_in[0];
    const float* dist   = (const float*)d_in[1];
    const int*   adj    = (const int*)  d_in[2];
    const float* fc_W   = (const float*)d_in[3];
    const float* fc_b   = (const float*)d_in[4];
    const float* conv_W = (const float*)d_in[5];
    const float* gat_W  = (const float*)d_in[6];
    const float* gat_a  = (const float*)d_in[7];
    const float* cls1_W = (const float*)d_in[8];
    const float* cls1_b = (const float*)d_in[9];
    const float* cls3_W = (const float*)d_in[10];
    const float* cls3_b = (const float*)d_in[11];
    float* out = (float*)d_out;

    float *h, *h0, *hi, *sup, *hp, *s1, *s2, *att, *h64;
    cudaGetSymbolAddress((void**)&h,   g_h);
    cudaGetSymbolAddress((void**)&h0,  g_h0);
    cudaGetSymbolAddress((void**)&hi,  g_hi);
    cudaGetSymbolAddress((void**)&sup, g_sup);
    cudaGetSymbolAddress((void**)&hp,  g_hp);
    cudaGetSymbolAddress((void**)&s1,  g_s1);
    cudaGetSymbolAddress((void**)&s2,  g_s2);
    cudaGetSymbolAddress((void**)&att, g_att);
    cudaGetSymbolAddress((void**)&h64, g_h64);

    dim3 gridBig (NHID / BN, NN / BM);   // 8 x 64
    const int n4 = NN * NHID / 4;

    // fc
    fc_kernel<<<NN, 256>>>(x, fc_W, fc_b, h, h0);

    // 7 GCNII layers
    for (int l = 1; l <= 7; l++) {
        float theta = logf(1.5f / (float)l + 1.0f);
        if (theta > 1.f) theta = 1.f;
        // hi = dist @ h
        sgemm_kernel<0><<<gridBig, 256>>>(dist, h, hi, NN, NHID, NN,
                                          nullptr, nullptr, 0.f);
        // sup = 0.3*hi + 0.7*h0
        support_kernel<<<2048, 256>>>(hi, h0, sup, n4);
        // h = relu(theta*(sup@W) + (1-theta)*sup + h)   (in-place safe)
        sgemm_kernel<1><<<gridBig, 256>>>(sup, conv_W + (size_t)(l - 1) * NHID * NHID,
                                          h, NN, NHID, NHID, sup, h, theta);
    }

    // GAT
    sgemm_kernel<0><<<gridBig, 256>>>(h, gat_W, hp, NN, NHID, NHID,
                                      nullptr, nullptr, 0.f);
    gat_s_kernel<<<NN, 256>>>(hp, gat_a, s1, s2);
    att_kernel<<<NN, 256>>>(adj, s1, s2, att);
    sgemm_kernel<0><<<gridBig, 256>>>(att, h, hi, NN, NHID, NN,
                                      nullptr, nullptr, 0.f);
    support_kernel<<<2048, 256>>>(hi, h0, sup, n4);
    {
        float theta = logf(1.5f / 9.0f + 1.0f);   // l = 9
        if (theta > 1.f) theta = 1.f;
        sgemm_kernel<2><<<gridBig, 256>>>(sup, gat_W, h, NN, NHID, NHID,
                                          sup, h, theta);
    }

    // classifier
    cls1_kernel<<<NN, 64>>>(h, cls1_W, cls1_b, h64);
    cls3_kernel<<<(NN + 255) / 256, 256>>>(h64, cls3_W, cls3_b, out);
}

// round 3
// speedup vs baseline: 7.4371x; 7.4371x over previous
#include <cuda_runtime.h>
#include <cuda_bf16.h>
#include <math.h>
#include <stdint.h>

#define NN    8192
#define NHID  1024
#define NFEAT 63

// ---------------- scratch (device globals; no allocation allowed) ----------
__device__ float g_h  [NN * NHID];
__device__ float g_h0 [NN * NHID];
__device__ float g_hi [NN * NHID];
__device__ float g_sup[NN * NHID];
__device__ float g_hp [NN * NHID];
__device__ float g_s1 [NN];
__device__ float g_s2 [NN];
__device__ __nv_bfloat16 g_att    [(size_t)NN * NN];     // 128 MB
__device__ __nv_bfloat16 g_dist_bf[(size_t)NN * NN];     // 128 MB
__device__ __nv_bfloat16 g_hbf    [NN * NHID];           // 16 MB
__device__ __nv_bfloat16 g_supbf  [NN * NHID];           // 16 MB
__device__ __nv_bfloat16 g_convWbf[7 * NHID * NHID];     // 14 MB
__device__ __nv_bfloat16 g_gatWbf [NHID * NHID];         // 2 MB
__device__ float g_h64[NN * 64];

// ======================= PTX helpers (base sm_103 features only) ===========
__device__ __forceinline__ uint32_t smem_u32(const void* p) {
    uint32_t a;
    asm("{ .reg .u64 t; cvta.to.shared.u64 t, %1; cvt.u32.u64 %0, t; }" : "=r"(a) : "l"(p));
    return a;
}
__device__ __forceinline__ void cp16(uint32_t saddr, const void* gaddr) {
    asm volatile("cp.async.cg.shared.global [%0], [%1], 16;" :: "r"(saddr), "l"(gaddr));
}
__device__ __forceinline__ void ldsm_x4(uint32_t* r, uint32_t addr) {
    asm volatile("ldmatrix.sync.aligned.m8n8.x4.shared.b16 {%0,%1,%2,%3}, [%4];"
                 : "=r"(r[0]), "=r"(r[1]), "=r"(r[2]), "=r"(r[3]) : "r"(addr));
}
__device__ __forceinline__ void ldsm_x4_t(uint32_t* r, uint32_t addr) {
    asm volatile("ldmatrix.sync.aligned.m8n8.x4.trans.shared.b16 {%0,%1,%2,%3}, [%4];"
                 : "=r"(r[0]), "=r"(r[1]), "=r"(r[2]), "=r"(r[3]) : "r"(addr));
}
__device__ __forceinline__ void mma16816(float* d, const uint32_t* a, const uint32_t* b) {
    asm volatile(
        "mma.sync.aligned.m16n8k16.row.col.f32.bf16.bf16.f32 "
        "{%0,%1,%2,%3}, {%4,%5,%6,%7}, {%8,%9}, {%0,%1,%2,%3};"
        : "+f"(d[0]), "+f"(d[1]), "+f"(d[2]), "+f"(d[3])
        : "r"(a[0]), "r"(a[1]), "r"(a[2]), "r"(a[3]), "r"(b[0]), "r"(b[1]));
}

// =============== bf16 HMMA GEMM: C[M,N] = A[M,K] @ B[K,N], fused epilogues ==
// EPI 0: C = acc
// EPI 1: C = relu(theta*acc + (1-theta)*S + H), Cbf = bf16(C)
// EPI 2: C = elu (theta*acc + (1-theta)*S + H)
// Block tile 128x128, BK=32, 4-stage cp.async pipeline, 256 threads (8 warps),
// warp tile 32x64 (2 m-tiles x 8 n-tiles of m16n8k16).
#define STAGE_BYTES 16384            // A 8KB + B 8KB
#define GEMM_SMEM   (4 * STAGE_BYTES)

template<int EPI>
__global__ void __launch_bounds__(256)
mma_gemm(const __nv_bfloat16* __restrict__ A, const __nv_bfloat16* __restrict__ B,
         float* __restrict__ C, int M, int N, int K,
         const float* __restrict__ S, const float* __restrict__ H,
         float theta, __nv_bfloat16* __restrict__ Cbf)
{
    extern __shared__ char smem[];
    const uint32_t sbase = smem_u32(smem);

    const int tid  = threadIdx.x;
    const int wid  = tid >> 5;
    const int lane = tid & 31;
    const int wm   = wid & 3;        // row warp (32 rows)
    const int wn   = wid >> 2;       // col warp (64 cols)
    const int bm = blockIdx.y, bn = blockIdx.x;
    const int T = K >> 5;            // BK = 32

    // per-thread load coordinates
    const int mA = tid >> 1;                 // 0..127 (A row within tile)
    const int cA = (tid & 1) * 2;            // A chunk base (of 4)
    const int kB = tid >> 3;                 // 0..31 (B row within tile)
    const int cB = tid & 7;                  // B chunk base (of 16)
    const __nv_bfloat16* Abase = A + (size_t)(bm * 128 + mA) * K;
    const __nv_bfloat16* Bbase = B + (size_t)kB * N + bn * 128;

    float acc[2][8][4];
    #pragma unroll
    for (int i = 0; i < 2; i++)
        #pragma unroll
        for (int j = 0; j < 8; j++)
            #pragma unroll
            for (int k = 0; k < 4; k++) acc[i][j][k] = 0.f;

    // swizzled smem offsets (constant per thread)
    const uint32_t swA0 = mA * 64 + ((cA + 0) ^ ((mA >> 1) & 3)) * 16;
    const uint32_t swA1 = mA * 64 + ((cA + 1) ^ ((mA >> 1) & 3)) * 16;
    const uint32_t swB0 = 8192 + kB * 256 + ((cB + 0) ^ (kB & 7)) * 16;
    const uint32_t swB1 = 8192 + kB * 256 + ((cB + 8) ^ (kB & 7)) * 16;

    auto load_tile = [&](int t) {
        const uint32_t sb = sbase + (t & 3) * STAGE_BYTES;
        const __nv_bfloat16* ga = Abase + t * 32;
        cp16(sb + swA0, ga + (cA + 0) * 8);
        cp16(sb + swA1, ga + (cA + 1) * 8);
        const __nv_bfloat16* gb = Bbase + (size_t)t * 32 * N;
        cp16(sb + swB0, gb + (cB + 0) * 8);
        cp16(sb + swB1, gb + (cB + 8) * 8);
    };

    // prologue: stages 0..2
    for (int t = 0; t < 3; t++) {
        if (t < T) load_tile(t);
        asm volatile("cp.async.commit_group;");
    }

    for (int t = 0; t < T; t++) {
        asm volatile("cp.async.wait_group 2;" ::: "memory");
        __syncthreads();
        const uint32_t sb = sbase + (t & 3) * STAGE_BYTES;

        #pragma unroll
        for (int ks = 0; ks < 2; ks++) {
            // A fragments (2 m-tiles)
            uint32_t a[2][4];
            {
                const int mr = wm * 32 + (lane & 15);
                const int ca = ks * 2 + (lane >> 4);
                #pragma unroll
                for (int mt = 0; mt < 2; mt++) {
                    const int m = mr + mt * 16;
                    ldsm_x4(a[mt], sb + m * 64 + ((ca ^ ((m >> 1) & 3)) * 16));
                }
            }
            // B fragments (8 n-tiles)
            uint32_t b[8][2];
            {
                const int g = lane >> 3, r = lane & 7;
                const int k = ks * 16 + (g & 1) * 8 + r;
                #pragma unroll
                for (int p = 0; p < 4; p++) {
                    const int nloc = wn * 64 + p * 16 + (g >> 1) * 8;
                    uint32_t t4[4];
                    ldsm_x4_t(t4, sb + 8192 + k * 256 + (((nloc >> 3) ^ (k & 7)) * 16));
                    b[p * 2][0] = t4[0]; b[p * 2][1] = t4[1];
                    b[p * 2 + 1][0] = t4[2]; b[p * 2 + 1][1] = t4[3];
                }
            }
            #pragma unroll
            for (int mt = 0; mt < 2; mt++)
                #pragma unroll
                for (int nt = 0; nt < 8; nt++)
                    mma16816(acc[mt][nt], a[mt], b[nt]);
        }
        __syncthreads();
        if (t + 3 < T) load_tile(t + 3);
        asm volatile("cp.async.commit_group;");
    }

    // epilogue
    const float omt = 1.0f - theta;
    #pragma unroll
    for (int mt = 0; mt < 2; mt++) {
        #pragma unroll
        for (int nt = 0; nt < 8; nt++) {
            float* d = acc[mt][nt];
            const int gr = bm * 128 + wm * 32 + mt * 16 + (lane >> 2);
            const int gc = bn * 128 + wn * 64 + nt * 8 + (lane & 3) * 2;
            size_t i0 = (size_t)gr * N + gc;
            size_t i1 = i0 + (size_t)8 * N;
            if (EPI == 0) {
                *(float2*)(C + i0) = make_float2(d[0], d[1]);
                *(float2*)(C + i1) = make_float2(d[2], d[3]);
            } else {
                float2 s0 = *(const float2*)(S + i0), s1 = *(const float2*)(S + i1);
                float2 h0v = *(const float2*)(H + i0), h1v = *(const float2*)(H + i1);
                float v0 = theta * d[0] + omt * s0.x + h0v.x;
                float v1 = theta * d[1] + omt * s0.y + h0v.y;
                float v2 = theta * d[2] + omt * s1.x + h1v.x;
                float v3 = theta * d[3] + omt * s1.y + h1v.y;
                if (EPI == 1) {
                    v0 = fmaxf(v0, 0.f); v1 = fmaxf(v1, 0.f);
                    v2 = fmaxf(v2, 0.f); v3 = fmaxf(v3, 0.f);
                    *(__nv_bfloat162*)(Cbf + i0) = __floats2bfloat162_rn(v0, v1);
                    *(__nv_bfloat162*)(Cbf + i1) = __floats2bfloat162_rn(v2, v3);
                } else {
                    v0 = (v0 > 0.f) ? v0 : (expf(v0) - 1.f);
                    v1 = (v1 > 0.f) ? v1 : (expf(v1) - 1.f);
                    v2 = (v2 > 0.f) ? v2 : (expf(v2) - 1.f);
                    v3 = (v3 > 0.f) ? v3 : (expf(v3) - 1.f);
                }
                *(float2*)(C + i0) = make_float2(v0, v1);
                *(float2*)(C + i1) = make_float2(v2, v3);
            }
        }
    }
}

// ---------------- fp32 -> bf16 elementwise ---------------------------------
__global__ void f32bf_kernel(const float* __restrict__ in, __nv_bfloat16* __restrict__ out, size_t n4)
{
    size_t i = (size_t)blockIdx.x * blockDim.x + threadIdx.x;
    size_t stride = (size_t)gridDim.x * blockDim.x;
    for (; i < n4; i += stride) {
        float4 v = ((const float4*)in)[i];
        __nv_bfloat162* o = (__nv_bfloat162*)out;
        o[2 * i]     = __floats2bfloat162_rn(v.x, v.y);
        o[2 * i + 1] = __floats2bfloat162_rn(v.z, v.w);
    }
}

// ---------------- fc: h = relu(x @ fc_W + b); writes h, h0, hbf ------------
__global__ void fc_kernel(const float* __restrict__ x, const float* __restrict__ W,
                          const float* __restrict__ b, float* __restrict__ h,
                          float* __restrict__ h0, __nv_bfloat16* __restrict__ hbf)
{
    int row = blockIdx.x;
    __shared__ float xs[NFEAT];
    int t = threadIdx.x;
    if (t < NFEAT) xs[t] = x[row * NFEAT + t];
    __syncthreads();
    for (int n = t; n < NHID; n += 256) {
        float acc = b[n];
        #pragma unroll 7
        for (int k = 0; k < NFEAT; k++) acc = fmaf(xs[k], W[k * NHID + n], acc);
        float v = fmaxf(acc, 0.f);
        size_t idx = (size_t)row * NHID + n;
        h[idx] = v;
        h0[idx] = v;
        hbf[idx] = __float2bfloat16(v);
    }
}

// ---------------- support = 0.3*hi + 0.7*h0 (fp32 + bf16) ------------------
__global__ void support_kernel(const float* __restrict__ hi, const float* __restrict__ h0,
                               float* __restrict__ sup, __nv_bfloat16* __restrict__ supbf, int n4)
{
    int i = blockIdx.x * blockDim.x + threadIdx.x;
    int stride = gridDim.x * blockDim.x;
    const float4* a = (const float4*)hi;
    const float4* b = (const float4*)h0;
    float4* o = (float4*)sup;
    __nv_bfloat162* ob = (__nv_bfloat162*)supbf;
    for (; i < n4; i += stride) {
        float4 u = a[i], v = b[i], r;
        r.x = 0.3f * u.x + 0.7f * v.x;
        r.y = 0.3f * u.y + 0.7f * v.y;
        r.z = 0.3f * u.z + 0.7f * v.z;
        r.w = 0.3f * u.w + 0.7f * v.w;
        o[i] = r;
        ob[2 * i]     = __floats2bfloat162_rn(r.x, r.y);
        ob[2 * i + 1] = __floats2bfloat162_rn(r.z, r.w);
    }
}

// ---------------- GAT score vectors ---------------------------------------
__global__ void gat_s_kernel(const float* __restrict__ hp, const float* __restrict__ a,
                             float* __restrict__ s1, float* __restrict__ s2)
{
    int row = blockIdx.x;
    int t = threadIdx.x;
    float p1 = 0.f, p2 = 0.f;
    const float* hrow = hp + (size_t)row * NHID;
    for (int k = t; k < NHID; k += 256) {
        float v = hrow[k];
        p1 = fmaf(v, a[k], p1);
        p2 = fmaf(v, a[NHID + k], p2);
    }
    __shared__ float r1[256], r2[256];
    r1[t] = p1; r2[t] = p2;
    __syncthreads();
    for (int off = 128; off > 0; off >>= 1) {
        if (t < off) { r1[t] += r1[t + off]; r2[t] += r2[t + off]; }
        __syncthreads();
    }
    if (t == 0) { s1[row] = r1[0]; s2[row] = r2[0]; }
}

// ---------------- masked row softmax -> bf16 attention matrix --------------
__global__ void att_kernel(const int* __restrict__ adj, const float* __restrict__ s1,
                           const float* __restrict__ s2, __nv_bfloat16* __restrict__ A)
{
    int row = blockIdx.x;
    int t = threadIdx.x;
    float si = s1[row];
    const int* arow = adj + (size_t)row * NN;

    float m = -1e30f, ssum = 0.f;
    for (int j = t; j < NN; j += 256) {
        if (arow[j] > 0) {
            float e = si + s2[j];
            e = (e > 0.f) ? e : 0.2f * e;
            if (e > m) { ssum = ssum * expf(m - e); m = e; }
            ssum += expf(e - m);
        }
    }
    __shared__ float sm[256], ss[256];
    sm[t] = m; ss[t] = ssum;
    __syncthreads();
    for (int off = 128; off > 0; off >>= 1) {
        if (t < off) {
            float m2 = sm[t + off], sv = ss[t + off];
            float M = fmaxf(sm[t], m2);
            ss[t] = ss[t] * expf(sm[t] - M) + sv * expf(m2 - M);
            sm[t] = M;
        }
        __syncthreads();
    }
    float M = sm[0], Ssum = ss[0];
    float inv = (Ssum > 0.f) ? (1.f / Ssum) : 0.f;

    __nv_bfloat16* Arow = A + (size_t)row * NN;
    for (int j = t; j < NN; j += 256) {
        float val = 0.f;
        if (arow[j] > 0) {
            float e = si + s2[j];
            e = (e > 0.f) ? e : 0.2f * e;
            val = expf(e - M) * inv;
        }
        Arow[j] = __float2bfloat16(val);
    }
}

// ---------------- classifier ------------------------------------------------
__global__ void cls1_kernel(const float* __restrict__ h, const float* __restrict__ W,
                            const float* __restrict__ b, float* __restrict__ out)
{
    int row = blockIdx.x;
    int t = threadIdx.x;                      // 64
    __shared__ float hs[NHID];
    for (int k = t; k < NHID; k += 64) hs[k] = h[(size_t)row * NHID + k];
    __syncthreads();
    float acc = b[t];
    for (int k = 0; k < NHID; k++) acc = fmaf(hs[k], W[k * 64 + t], acc);
    out[row * 64 + t] = fmaxf(acc, 0.f);
}

__global__ void cls3_kernel(const float* __restrict__ h64, const float* __restrict__ W,
                            const float* __restrict__ b, float* __restrict__ out)
{
    int i = blockIdx.x * blockDim.x + threadIdx.x;
    if (i < NN) {
        float acc = b[0];
        #pragma unroll 16
        for (int k = 0; k < 64; k++) acc = fmaf(h64[i * 64 + k], W[k], acc);
        out[i] = 1.f / (1.f + expf(-acc));
    }
}

// ---------------------------------------------------------------------------
extern "C" void kernel_launch(void* const* d_in, const int* in_sizes, int n_in,
                              void* d_out, int out_size)
{
    const float* x      = (const float*)d_in[0];
    const float* dist   = (const float*)d_in[1];
    const int*   adj    = (const int*)  d_in[2];
    const float* fc_W   = (const float*)d_in[3];
    const float* fc_b   = (const float*)d_in[4];
    const float* conv_W = (const float*)d_in[5];
    const float* gat_W  = (const float*)d_in[6];
    const float* gat_a  = (const float*)d_in[7];
    const float* cls1_W = (const float*)d_in[8];
    const float* cls1_b = (const float*)d_in[9];
    const float* cls3_W = (const float*)d_in[10];
    const float* cls3_b = (const float*)d_in[11];
    float* out = (float*)d_out;

    float *h, *h0, *hi, *sup, *hp, *s1, *s2, *h64;
    __nv_bfloat16 *att, *dist_bf, *hbf, *supbf, *convWbf, *gatWbf;
    cudaGetSymbolAddress((void**)&h,   g_h);
    cudaGetSymbolAddress((void**)&h0,  g_h0);
    cudaGetSymbolAddress((void**)&hi,  g_hi);
    cudaGetSymbolAddress((void**)&sup, g_sup);
    cudaGetSymbolAddress((void**)&hp,  g_hp);
    cudaGetSymbolAddress((void**)&s1,  g_s1);
    cudaGetSymbolAddress((void**)&s2,  g_s2);
    cudaGetSymbolAddress((void**)&att, g_att);
    cudaGetSymbolAddress((void**)&dist_bf, g_dist_bf);
    cudaGetSymbolAddress((void**)&hbf, g_hbf);
    cudaGetSymbolAddress((void**)&supbf, g_supbf);
    cudaGetSymbolAddress((void**)&convWbf, g_convWbf);
    cudaGetSymbolAddress((void**)&gatWbf, g_gatWbf);
    cudaGetSymbolAddress((void**)&h64, g_h64);

    cudaFuncSetAttribute(mma_gemm<0>, cudaFuncAttributeMaxDynamicSharedMemorySize, GEMM_SMEM);
    cudaFuncSetAttribute(mma_gemm<1>, cudaFuncAttributeMaxDynamicSharedMemorySize, GEMM_SMEM);
    cudaFuncSetAttribute(mma_gemm<2>, cudaFuncAttributeMaxDynamicSharedMemorySize, GEMM_SMEM);

    dim3 grid(NHID / 128, NN / 128);   // (8, 64)
    const int n4 = NN * NHID / 4;

    // one-time conversions
    f32bf_kernel<<<2048, 256>>>(dist, dist_bf, (size_t)NN * NN / 4);
    f32bf_kernel<<<512, 256>>>(conv_W, convWbf, (size_t)7 * NHID * NHID / 4);
    f32bf_kernel<<<256, 256>>>(gat_W, gatWbf, (size_t)NHID * NHID / 4);

    // fc
    fc_kernel<<<NN, 256>>>(x, fc_W, fc_b, h, h0, hbf);

    // 7 GCNII layers
    for (int l = 1; l <= 7; l++) {
        float theta = logf(1.5f / (float)l + 1.0f);
        if (theta > 1.f) theta = 1.f;
        // hi = dist @ h
        mma_gemm<0><<<grid, 256, GEMM_SMEM>>>(dist_bf, hbf, hi, NN, NHID, NN,
                                              nullptr, nullptr, 0.f, nullptr);
        // sup = 0.3*hi + 0.7*h0 (+ bf16)
        support_kernel<<<2048, 256>>>(hi, h0, sup, supbf, n4);
        // h = relu(theta*(sup@W) + (1-theta)*sup + h), + hbf
        mma_gemm<1><<<grid, 256, GEMM_SMEM>>>(supbf, convWbf + (size_t)(l - 1) * NHID * NHID,
                                              h, NN, NHID, NHID, sup, h, theta, hbf);
    }

    // GAT
    mma_gemm<0><<<grid, 256, GEMM_SMEM>>>(hbf, gatWbf, hp, NN, NHID, NHID,
                                          nullptr, nullptr, 0.f, nullptr);
    gat_s_kernel<<<NN, 256>>>(hp, gat_a, s1, s2);
    att_kernel<<<NN, 256>>>(adj, s1, s2, att);
    mma_gemm<0><<<grid, 256, GEMM_SMEM>>>(att, hbf, hi, NN, NHID, NN,
                                          nullptr, nullptr, 0.f, nullptr);
    support_kernel<<<2048, 256>>>(hi, h0, sup, supbf, n4);
    {
        float theta = logf(1.5f / 9.0f + 1.0f);
        if (theta > 1.f) theta = 1.f;
        mma_gemm<2><<<grid, 256, GEMM_SMEM>>>(supbf, gatWbf, h, NN, NHID, NHID,
                                              sup, h, theta, nullptr);
    }

    // classifier
    cls1_kernel<<<NN, 64>>>(h, cls1_W, cls1_b, h64);
    cls3_kernel<<<(NN + 255) / 256, 256>>>(h64, cls3_W, cls3_b, out);
}

// round 4
// speedup vs baseline: 7.5406x; 1.0139x over previous
#include <cuda_runtime.h>
#include <cuda_bf16.h>
#include <math.h>
#include <stdint.h>

#define NN    8192
#define NHID  1024
#define NFEAT 63

// ---------------- scratch (device globals; no allocation allowed) ----------
__device__ float g_h  [NN * NHID];
__device__ float g_h0 [NN * NHID];
__device__ float g_sup[NN * NHID];
__device__ float g_s1 [NN];
__device__ float g_s2 [NN];
__device__ float g_w1 [NHID];
__device__ float g_w2 [NHID];
__device__ __nv_bfloat16 g_att    [(size_t)NN * NN];     // 128 MB
__device__ __nv_bfloat16 g_dist_bf[(size_t)NN * NN];     // 128 MB
__device__ __nv_bfloat16 g_hbf    [NN * NHID];           // 16 MB
__device__ __nv_bfloat16 g_supbf  [NN * NHID];           // 16 MB
__device__ __nv_bfloat16 g_convWbf[7 * NHID * NHID];     // 14 MB
__device__ __nv_bfloat16 g_gatWbf [NHID * NHID];         // 2 MB
__device__ float g_h64[NN * 64];

// ======================= PTX helpers (base sm_103 features only) ===========
__device__ __forceinline__ uint32_t smem_u32(const void* p) {
    uint32_t a;
    asm("{ .reg .u64 t; cvta.to.shared.u64 t, %1; cvt.u32.u64 %0, t; }" : "=r"(a) : "l"(p));
    return a;
}
__device__ __forceinline__ void cp16(uint32_t saddr, const void* gaddr) {
    asm volatile("cp.async.cg.shared.global [%0], [%1], 16;" :: "r"(saddr), "l"(gaddr));
}
__device__ __forceinline__ void ldsm_x4(uint32_t* r, uint32_t addr) {
    asm volatile("ldmatrix.sync.aligned.m8n8.x4.shared.b16 {%0,%1,%2,%3}, [%4];"
                 : "=r"(r[0]), "=r"(r[1]), "=r"(r[2]), "=r"(r[3]) : "r"(addr));
}
__device__ __forceinline__ void ldsm_x4_t(uint32_t* r, uint32_t addr) {
    asm volatile("ldmatrix.sync.aligned.m8n8.x4.trans.shared.b16 {%0,%1,%2,%3}, [%4];"
                 : "=r"(r[0]), "=r"(r[1]), "=r"(r[2]), "=r"(r[3]) : "r"(addr));
}
__device__ __forceinline__ void mma16816(float* d, const uint32_t* a, const uint32_t* b) {
    asm volatile(
        "mma.sync.aligned.m16n8k16.row.col.f32.bf16.bf16.f32 "
        "{%0,%1,%2,%3}, {%4,%5,%6,%7}, {%8,%9}, {%0,%1,%2,%3};"
        : "+f"(d[0]), "+f"(d[1]), "+f"(d[2]), "+f"(d[3])
        : "r"(a[0]), "r"(a[1]), "r"(a[2]), "r"(a[3]), "r"(b[0]), "r"(b[1]));
}

// =============== bf16 HMMA GEMM: C[M,N] = A[M,K] @ B[K,N], fused epilogues ==
// EPI 1: C = relu(theta*acc + (1-theta)*S + H), Cbf = bf16(C)
// EPI 2: C = elu (theta*acc + (1-theta)*S + H)
// EPI 3: C = 0.3*acc + 0.7*H,  Cbf = bf16(C)        (fused "support")
#define STAGE_BYTES 16384            // A 8KB + B 8KB
#define GEMM_SMEM   (4 * STAGE_BYTES)

template<int EPI>
__global__ void __launch_bounds__(256)
mma_gemm(const __nv_bfloat16* __restrict__ A, const __nv_bfloat16* __restrict__ B,
         float* __restrict__ C, int M, int N, int K,
         const float* __restrict__ S, const float* __restrict__ H,
         float theta, __nv_bfloat16* __restrict__ Cbf)
{
    extern __shared__ char smem[];
    const uint32_t sbase = smem_u32(smem);

    const int tid  = threadIdx.x;
    const int wid  = tid >> 5;
    const int lane = tid & 31;
    const int wm   = wid & 3;        // row warp (32 rows)
    const int wn   = wid >> 2;       // col warp (64 cols)
    const int bm = blockIdx.y, bn = blockIdx.x;
    const int T = K >> 5;            // BK = 32

    const int mA = tid >> 1;
    const int cA = (tid & 1) * 2;
    const int kB = tid >> 3;
    const int cB = tid & 7;
    const __nv_bfloat16* Abase = A + (size_t)(bm * 128 + mA) * K;
    const __nv_bfloat16* Bbase = B + (size_t)kB * N + bn * 128;

    float acc[2][8][4];
    #pragma unroll
    for (int i = 0; i < 2; i++)
        #pragma unroll
        for (int j = 0; j < 8; j++)
            #pragma unroll
            for (int k = 0; k < 4; k++) acc[i][j][k] = 0.f;

    const uint32_t swA0 = mA * 64 + ((cA + 0) ^ ((mA >> 1) & 3)) * 16;
    const uint32_t swA1 = mA * 64 + ((cA + 1) ^ ((mA >> 1) & 3)) * 16;
    const uint32_t swB0 = 8192 + kB * 256 + ((cB + 0) ^ (kB & 7)) * 16;
    const uint32_t swB1 = 8192 + kB * 256 + ((cB + 8) ^ (kB & 7)) * 16;

    auto load_tile = [&](int t) {
        const uint32_t sb = sbase + (t & 3) * STAGE_BYTES;
        const __nv_bfloat16* ga = Abase + t * 32;
        cp16(sb + swA0, ga + (cA + 0) * 8);
        cp16(sb + swA1, ga + (cA + 1) * 8);
        const __nv_bfloat16* gb = Bbase + (size_t)t * 32 * N;
        cp16(sb + swB0, gb + (cB + 0) * 8);
        cp16(sb + swB1, gb + (cB + 8) * 8);
    };

    for (int t = 0; t < 3; t++) {
        if (t < T) load_tile(t);
        asm volatile("cp.async.commit_group;");
    }

    for (int t = 0; t < T; t++) {
        asm volatile("cp.async.wait_group 2;" ::: "memory");
        __syncthreads();
        const uint32_t sb = sbase + (t & 3) * STAGE_BYTES;

        #pragma unroll
        for (int ks = 0; ks < 2; ks++) {
            uint32_t a[2][4];
            {
                const int mr = wm * 32 + (lane & 15);
                const int ca = ks * 2 + (lane >> 4);
                #pragma unroll
                for (int mt = 0; mt < 2; mt++) {
                    const int m = mr + mt * 16;
                    ldsm_x4(a[mt], sb + m * 64 + ((ca ^ ((m >> 1) & 3)) * 16));
                }
            }
            uint32_t b[8][2];
            {
                const int g = lane >> 3, r = lane & 7;
                const int k = ks * 16 + (g & 1) * 8 + r;
                #pragma unroll
                for (int p = 0; p < 4; p++) {
                    const int nloc = wn * 64 + p * 16 + (g >> 1) * 8;
                    uint32_t t4[4];
                    ldsm_x4_t(t4, sb + 8192 + k * 256 + (((nloc >> 3) ^ (k & 7)) * 16));
                    b[p * 2][0] = t4[0]; b[p * 2][1] = t4[1];
                    b[p * 2 + 1][0] = t4[2]; b[p * 2 + 1][1] = t4[3];
                }
            }
            #pragma unroll
            for (int mt = 0; mt < 2; mt++)
                #pragma unroll
                for (int nt = 0; nt < 8; nt++)
                    mma16816(acc[mt][nt], a[mt], b[nt]);
        }
        __syncthreads();
        if (t + 3 < T) load_tile(t + 3);
        asm volatile("cp.async.commit_group;");
    }

    const float omt = 1.0f - theta;
    #pragma unroll
    for (int mt = 0; mt < 2; mt++) {
        #pragma unroll
        for (int nt = 0; nt < 8; nt++) {
            float* d = acc[mt][nt];
            const int gr = bm * 128 + wm * 32 + mt * 16 + (lane >> 2);
            const int gc = bn * 128 + wn * 64 + nt * 8 + (lane & 3) * 2;
            size_t i0 = (size_t)gr * N + gc;
            size_t i1 = i0 + (size_t)8 * N;
            float2 h0v = *(const float2*)(H + i0), h1v = *(const float2*)(H + i1);
            float v0, v1, v2, v3;
            if (EPI == 3) {
                v0 = 0.3f * d[0] + 0.7f * h0v.x;
                v1 = 0.3f * d[1] + 0.7f * h0v.y;
                v2 = 0.3f * d[2] + 0.7f * h1v.x;
                v3 = 0.3f * d[3] + 0.7f * h1v.y;
                *(__nv_bfloat162*)(Cbf + i0) = __floats2bfloat162_rn(v0, v1);
                *(__nv_bfloat162*)(Cbf + i1) = __floats2bfloat162_rn(v2, v3);
            } else {
                float2 s0 = *(const float2*)(S + i0), s1 = *(const float2*)(S + i1);
                v0 = theta * d[0] + omt * s0.x + h0v.x;
                v1 = theta * d[1] + omt * s0.y + h0v.y;
                v2 = theta * d[2] + omt * s1.x + h1v.x;
                v3 = theta * d[3] + omt * s1.y + h1v.y;
                if (EPI == 1) {
                    v0 = fmaxf(v0, 0.f); v1 = fmaxf(v1, 0.f);
                    v2 = fmaxf(v2, 0.f); v3 = fmaxf(v3, 0.f);
                    *(__nv_bfloat162*)(Cbf + i0) = __floats2bfloat162_rn(v0, v1);
                    *(__nv_bfloat162*)(Cbf + i1) = __floats2bfloat162_rn(v2, v3);
                } else {
                    v0 = (v0 > 0.f) ? v0 : (expf(v0) - 1.f);
                    v1 = (v1 > 0.f) ? v1 : (expf(v1) - 1.f);
                    v2 = (v2 > 0.f) ? v2 : (expf(v2) - 1.f);
                    v3 = (v3 > 0.f) ? v3 : (expf(v3) - 1.f);
                }
            }
            *(float2*)(C + i0) = make_float2(v0, v1);
            *(float2*)(C + i1) = make_float2(v2, v3);
        }
    }
}

// ---------------- fp32 -> bf16 elementwise ---------------------------------
__global__ void f32bf_kernel(const float* __restrict__ in, __nv_bfloat16* __restrict__ out, size_t n4)
{
    size_t i = (size_t)blockIdx.x * blockDim.x + threadIdx.x;
    size_t stride = (size_t)gridDim.x * blockDim.x;
    for (; i < n4; i += stride) {
        float4 v = ((const float4*)in)[i];
        __nv_bfloat162* o = (__nv_bfloat162*)out;
        o[2 * i]     = __floats2bfloat162_rn(v.x, v.y);
        o[2 * i + 1] = __floats2bfloat162_rn(v.z, v.w);
    }
}

// ---------------- fc (tiled): h = relu(x @ fc_W + b); writes h, h0, hbf ----
// block: 128 rows x 256 cols. smem: W slab [63][256] + x tile [128][64 pad]
#define FC_SMEM (63 * 256 * 4 + 128 * 64 * 4)
__global__ void __launch_bounds__(256)
fc_kernel(const float* __restrict__ x, const float* __restrict__ W,
          const float* __restrict__ b, float* __restrict__ h,
          float* __restrict__ h0, __nv_bfloat16* __restrict__ hbf)
{
    extern __shared__ float fsm[];
    float* Ws = fsm;               // [63][256]
    float* xs = fsm + 63 * 256;    // [128][64]
    const int t = threadIdx.x;
    const int bn = blockIdx.x;     // 0..3
    const int bm = blockIdx.y;     // 0..63

    #pragma unroll 4
    for (int k = 0; k < NFEAT; k++)
        Ws[k * 256 + t] = W[k * NHID + bn * 256 + t];
    for (int i = t; i < 128 * NFEAT; i += 256) {
        int r = i / NFEAT, c = i % NFEAT;
        xs[r * 64 + c] = x[(size_t)(bm * 128 + r) * NFEAT + c];
    }
    __syncthreads();

    const float bias = b[bn * 256 + t];
    for (int r = 0; r < 128; r++) {
        float acc = bias;
        #pragma unroll 21
        for (int k = 0; k < NFEAT; k++)
            acc = fmaf(xs[r * 64 + k], Ws[k * 256 + t], acc);
        float v = fmaxf(acc, 0.f);
        size_t idx = (size_t)(bm * 128 + r) * NHID + bn * 256 + t;
        h[idx] = v;
        h0[idx] = v;
        hbf[idx] = __float2bfloat16(v);
    }
}

// ---------------- w1 = gat_W @ a1, w2 = gat_W @ a2 -------------------------
__global__ void gat_w12_kernel(const float* __restrict__ W, const float* __restrict__ a,
                               float* __restrict__ w1, float* __restrict__ w2)
{
    int k = blockIdx.x;
    int t = threadIdx.x;                      // 256
    float p1 = 0.f, p2 = 0.f;
    const float* Wrow = W + (size_t)k * NHID;
    for (int n = t; n < NHID; n += 256) {
        float v = Wrow[n];
        p1 = fmaf(v, a[n], p1);
        p2 = fmaf(v, a[NHID + n], p2);
    }
    __shared__ float r1[256], r2[256];
    r1[t] = p1; r2[t] = p2;
    __syncthreads();
    for (int off = 128; off > 0; off >>= 1) {
        if (t < off) { r1[t] += r1[t + off]; r2[t] += r2[t + off]; }
        __syncthreads();
    }
    if (t == 0) { w1[k] = r1[0]; w2[k] = r2[0]; }
}

// ---------------- s1 = h @ w1, s2 = h @ w2 ---------------------------------
__global__ void gat_s_kernel(const float* __restrict__ h, const float* __restrict__ w1,
                             const float* __restrict__ w2,
                             float* __restrict__ s1, float* __restrict__ s2)
{
    int row = blockIdx.x;
    int t = threadIdx.x;
    float p1 = 0.f, p2 = 0.f;
    const float* hrow = h + (size_t)row * NHID;
    for (int k = t; k < NHID; k += 256) {
        float v = hrow[k];
        p1 = fmaf(v, w1[k], p1);
        p2 = fmaf(v, w2[k], p2);
    }
    __shared__ float r1[256], r2[256];
    r1[t] = p1; r2[t] = p2;
    __syncthreads();
    for (int off = 128; off > 0; off >>= 1) {
        if (t < off) { r1[t] += r1[t + off]; r2[t] += r2[t + off]; }
        __syncthreads();
    }
    if (t == 0) { s1[row] = r1[0]; s2[row] = r2[0]; }
}

// ---------------- masked row softmax -> bf16 attention (1-pass adj) --------
__global__ void att_kernel(const int* __restrict__ adj, const float* __restrict__ s1,
                           const float* __restrict__ s2, __nv_bfloat16* __restrict__ A)
{
    const int row = blockIdx.x;
    const int t = threadIdx.x;
    const int w = t >> 5, lane = t & 31;
    const float si = s1[row];
    const int* arow = adj + (size_t)row * NN;

    __shared__ uint32_t mask[NN / 32];        // 256 words = 1KB
    float m = -1e30f, ssum = 0.f;

    for (int it = 0; it < NN / 256; it++) {   // 32 iterations
        int j = (it * 8 + w) * 32 + lane;
        int av = arow[j];
        uint32_t mk = __ballot_sync(0xffffffff, av > 0);
        if (lane == 0) mask[it * 8 + w] = mk;
        if (av > 0) {
            float e = si + s2[j];
            e = (e > 0.f) ? e : 0.2f * e;
            if (e > m) { ssum = ssum * expf(m - e); m = e; }
            ssum += expf(e - m);
        }
    }

    __shared__ float sm[256], ss[256];
    sm[t] = m; ss[t] = ssum;
    __syncthreads();
    for (int off = 128; off > 0; off >>= 1) {
        if (t < off) {
            float m2 = sm[t + off], sv = ss[t + off];
            float M = fmaxf(sm[t], m2);
            ss[t] = ss[t] * expf(sm[t] - M) + sv * expf(m2 - M);
            sm[t] = M;
        }
        __syncthreads();
    }
    const float M = sm[0], Ssum = ss[0];
    const float inv = (Ssum > 0.f) ? (1.f / Ssum) : 0.f;

    __nv_bfloat16* Arow = A + (size_t)row * NN;
    for (int j0 = t * 2; j0 < NN; j0 += 512) {
        float v0 = 0.f, v1 = 0.f;
        uint32_t mk = mask[j0 >> 5];
        if ((mk >> (j0 & 31)) & 1) {
            float e = si + s2[j0];
            e = (e > 0.f) ? e : 0.2f * e;
            v0 = expf(e - M) * inv;
        }
        if ((mk >> ((j0 + 1) & 31)) & 1) {
            float e = si + s2[j0 + 1];
            e = (e > 0.f) ? e : 0.2f * e;
            v1 = expf(e - M) * inv;
        }
        *(__nv_bfloat162*)(Arow + j0) = __floats2bfloat162_rn(v0, v1);
    }
}

// ---------------- classifier ------------------------------------------------
__global__ void cls1_kernel(const float* __restrict__ h, const float* __restrict__ W,
                            const float* __restrict__ b, float* __restrict__ out)
{
    int row = blockIdx.x;
    int t = threadIdx.x;                      // 64
    __shared__ float hs[NHID];
    for (int k = t; k < NHID; k += 64) hs[k] = h[(size_t)row * NHID + k];
    __syncthreads();
    float acc = b[t];
    for (int k = 0; k < NHID; k++) acc = fmaf(hs[k], W[k * 64 + t], acc);
    out[row * 64 + t] = fmaxf(acc, 0.f);
}

__global__ void cls3_kernel(const float* __restrict__ h64, const float* __restrict__ W,
                            const float* __restrict__ b, float* __restrict__ out)
{
    int i = blockIdx.x * blockDim.x + threadIdx.x;
    if (i < NN) {
        float acc = b[0];
        #pragma unroll 16
        for (int k = 0; k < 64; k++) acc = fmaf(h64[i * 64 + k], W[k], acc);
        out[i] = 1.f / (1.f + expf(-acc));
    }
}

// ---------------------------------------------------------------------------
extern "C" void kernel_launch(void* const* d_in, const int* in_sizes, int n_in,
                              void* d_out, int out_size)
{
    const float* x      = (const float*)d_in[0];
    const float* dist   = (const float*)d_in[1];
    const int*   adj    = (const int*)  d_in[2];
    const float* fc_W   = (const float*)d_in[3];
    const float* fc_b   = (const float*)d_in[4];
    const float* conv_W = (const float*)d_in[5];
    const float* gat_W  = (const float*)d_in[6];
    const float* gat_a  = (const float*)d_in[7];
    const float* cls1_W = (const float*)d_in[8];
    const float* cls1_b = (const float*)d_in[9];
    const float* cls3_W = (const float*)d_in[10];
    const float* cls3_b = (const float*)d_in[11];
    float* out = (float*)d_out;

    float *h, *h0, *sup, *s1, *s2, *w1, *w2, *h64;
    __nv_bfloat16 *att, *dist_bf, *hbf, *supbf, *convWbf, *gatWbf;
    cudaGetSymbolAddress((void**)&h,   g_h);
    cudaGetSymbolAddress((void**)&h0,  g_h0);
    cudaGetSymbolAddress((void**)&sup, g_sup);
    cudaGetSymbolAddress((void**)&s1,  g_s1);
    cudaGetSymbolAddress((void**)&s2,  g_s2);
    cudaGetSymbolAddress((void**)&w1,  g_w1);
    cudaGetSymbolAddress((void**)&w2,  g_w2);
    cudaGetSymbolAddress((void**)&att, g_att);
    cudaGetSymbolAddress((void**)&dist_bf, g_dist_bf);
    cudaGetSymbolAddress((void**)&hbf, g_hbf);
    cudaGetSymbolAddress((void**)&supbf, g_supbf);
    cudaGetSymbolAddress((void**)&convWbf, g_convWbf);
    cudaGetSymbolAddress((void**)&gatWbf, g_gatWbf);
    cudaGetSymbolAddress((void**)&h64, g_h64);

    cudaFuncSetAttribute(mma_gemm<1>, cudaFuncAttributeMaxDynamicSharedMemorySize, GEMM_SMEM);
    cudaFuncSetAttribute(mma_gemm<2>, cudaFuncAttributeMaxDynamicSharedMemorySize, GEMM_SMEM);
    cudaFuncSetAttribute(mma_gemm<3>, cudaFuncAttributeMaxDynamicSharedMemorySize, GEMM_SMEM);
    cudaFuncSetAttribute(fc_kernel,   cudaFuncAttributeMaxDynamicSharedMemorySize, FC_SMEM);

    dim3 grid(NHID / 128, NN / 128);   // (8, 64)

    // one-time conversions
    f32bf_kernel<<<2048, 256>>>(dist, dist_bf, (size_t)NN * NN / 4);
    f32bf_kernel<<<512, 256>>>(conv_W, convWbf, (size_t)7 * NHID * NHID / 4);
    f32bf_kernel<<<256, 256>>>(gat_W, gatWbf, (size_t)NHID * NHID / 4);

    // fc (tiled)
    dim3 fcGrid(NHID / 256, NN / 128);
    fc_kernel<<<fcGrid, 256, FC_SMEM>>>(x, fc_W, fc_b, h, h0, hbf);

    // 7 GCNII layers: (dist@h fused with support) then (conv + residual + relu)
    for (int l = 1; l <= 7; l++) {
        float theta = logf(1.5f / (float)l + 1.0f);
        if (theta > 1.f) theta = 1.f;
        mma_gemm<3><<<grid, 256, GEMM_SMEM>>>(dist_bf, hbf, sup, NN, NHID, NN,
                                              nullptr, h0, 0.f, supbf);
        mma_gemm<1><<<grid, 256, GEMM_SMEM>>>(supbf, convWbf + (size_t)(l - 1) * NHID * NHID,
                                              h, NN, NHID, NHID, sup, h, theta, hbf);
    }

    // GAT (hp GEMM eliminated algebraically)
    gat_w12_kernel<<<NHID, 256>>>(gat_W, gat_a, w1, w2);
    gat_s_kernel<<<NN, 256>>>(h, w1, w2, s1, s2);
    att_kernel<<<NN, 256>>>(adj, s1, s2, att);
    mma_gemm<3><<<grid, 256, GEMM_SMEM>>>(att, hbf, sup, NN, NHID, NN,
                                          nullptr, h0, 0.f, supbf);
    {
        float theta = logf(1.5f / 9.0f + 1.0f);
        if (theta > 1.f) theta = 1.f;
        mma_gemm<2><<<grid, 256, GEMM_SMEM>>>(supbf, gatWbf, h, NN, NHID, NHID,
                                              sup, h, theta, nullptr);
    }

    // classifier
    cls1_kernel<<<NN, 64>>>(h, cls1_W, cls1_b, h64);
    cls3_kernel<<<(NN + 255) / 256, 256>>>(h64, cls3_W, cls3_b, out);
}